// round 12
// baseline (speedup 1.0000x reference)
#include <cuda_runtime.h>
#include <cuda_fp16.h>
#include <cstdint>

// ============================================================================
// y = x @ W_mod^T ; W_mod = W with values*0.1 scattered at flip_idx (last wins)
// x:[256,4096] f32, W:[4096,4096] f32, flip:[1M] int32, vals:[1M] f32 -> y f32
// R12: GEMM N-tile 32, 256 CTAs, 2 CTAs/SM (4 warps/SMSP) to probe/exploit
// HMMA issue rate; stage1 W-convert 2x float4/thread.
// ============================================================================

#define O_DIM  4096
#define I_DIM  4096
#define B_ROWS 256
#define W_ELEMS (O_DIM * I_DIM)
#define X_ELEMS (B_ROWS * I_DIM)

#define SW128(b) ((b) ^ (((b) >> 3) & 0x70))

// Chunk-major swizzled layouts (K-chunk = 128 cols = 256B, two 128B sub-tiles):
//  g_xh: [chunk 32][m_tile 2][ sub0 16KB | sub1 16KB ]          (64KB/chunk)
//  g_wh: [chunk 32][n_grp 64][ sub0 8KB (cols 0-63) | sub1 8KB ] (1MB/chunk)
__device__ __align__(16) __half g_xh[X_ELEMS];
__device__ __align__(16) __half g_wh[W_ELEMS];
// zero at module load; atomicExch in scatter restores all-zero every launch
__device__ int g_aux[W_ELEMS];

// ----------------------------------------------------------------------------
// Stage 1: fused [winner election | x convert | W convert x2-unrolled]
// ----------------------------------------------------------------------------
static constexpr int NB_WIN = 977;                 // ceil(1e6/1024), 4 idx/thr
static constexpr int NB_CX  = X_ELEMS / 4 / 256;   // 1024
static constexpr int NB_CW  = W_ELEMS / 8 / 256;   // 8192 (2 float4/thread)

__device__ __forceinline__ void conv_w_one(const float4* __restrict__ w, int i) {
    const int o = i >> 10, kq = (i & 1023) << 2;
    float4 v = __ldcs(w + i);
    uint2 p = make_uint2(
        (uint32_t)__half_as_ushort(__float2half_rn(v.x)) |
        ((uint32_t)__half_as_ushort(__float2half_rn(v.y)) << 16),
        (uint32_t)__half_as_ushort(__float2half_rn(v.z)) |
        ((uint32_t)__half_as_ushort(__float2half_rn(v.w)) << 16));
    const int c = kq >> 7, k0 = kq & 127, sub = k0 >> 6, kk = k0 & 63;
    char* dst = reinterpret_cast<char*>(g_wh)
              + (size_t)c * 1048576 + (o >> 6) * 16384 + sub * 8192
              + SW128((o & 63) * 128 + kk * 2);
    __stcs(reinterpret_cast<uint2*>(dst), p);
}

__global__ void __launch_bounds__(256) stage1_kernel(
    const float4* __restrict__ x, const float4* __restrict__ w,
    const int* __restrict__ flip, int n) {
    const int bid = blockIdx.x, tid = threadIdx.x;
    if (bid < NB_WIN) {
        const int base = bid * 1024 + tid * 4;
        if (base + 3 < n) {
            const int4 f = *reinterpret_cast<const int4*>(flip + base);
            atomicMax(&g_aux[f.x], base + 1);
            atomicMax(&g_aux[f.y], base + 2);
            atomicMax(&g_aux[f.z], base + 3);
            atomicMax(&g_aux[f.w], base + 4);
        } else {
            for (int k = 0; k < 4; ++k)
                if (base + k < n) atomicMax(&g_aux[flip[base + k]], base + k + 1);
        }
    } else if (bid < NB_WIN + NB_CX) {
        const int i = (bid - NB_WIN) * 256 + tid;
        const int m = i >> 10, kq = (i & 1023) << 2;      // 4 k-elems
        float4 v = __ldcs(x + i);
        uint2 p = make_uint2(
            (uint32_t)__half_as_ushort(__float2half_rn(v.x)) |
            ((uint32_t)__half_as_ushort(__float2half_rn(v.y)) << 16),
            (uint32_t)__half_as_ushort(__float2half_rn(v.z)) |
            ((uint32_t)__half_as_ushort(__float2half_rn(v.w)) << 16));
        const int c = kq >> 7, k0 = kq & 127, sub = k0 >> 6, kk = k0 & 63;
        char* dst = reinterpret_cast<char*>(g_xh)
                  + (size_t)c * 65536 + (m >> 7) * 32768 + sub * 16384
                  + SW128((m & 127) * 128 + kk * 2);
        __stcs(reinterpret_cast<uint2*>(dst), p);
    } else {
        const int i0 = (bid - NB_WIN - NB_CX) * 512 + tid;
        conv_w_one(w, i0);
        conv_w_one(w, i0 + 256);
    }
}

// ----------------------------------------------------------------------------
// Stage 2: exchange-scatter (8 idx/thread, R10-exact)
// ----------------------------------------------------------------------------
__device__ __forceinline__ void scatter_one(int pos, float v) {
    const int o = pos >> 12, k = pos & 4095;
    const int c = k >> 7, k0 = k & 127, sub = k0 >> 6, kk = k0 & 63;
    char* dst = reinterpret_cast<char*>(g_wh)
              + (size_t)c * 1048576 + (o >> 6) * 16384 + sub * 8192
              + SW128((o & 63) * 128 + kk * 2);
    *reinterpret_cast<__half*>(dst) = __float2half_rn(v);
}

__global__ void __launch_bounds__(256) scatter_kernel(
    const int* __restrict__ flip, const float* __restrict__ vals, int n) {
    const int base = (blockIdx.x * 256 + threadIdx.x) * 8;
    if (base + 7 < n) {
        const int4 f0 = *reinterpret_cast<const int4*>(flip + base);
        const int4 f1 = *reinterpret_cast<const int4*>(flip + base + 4);
        int pos[8] = {f0.x, f0.y, f0.z, f0.w, f1.x, f1.y, f1.z, f1.w};
        int old[8];
        #pragma unroll
        for (int k = 0; k < 8; ++k) old[k] = atomicExch(&g_aux[pos[k]], 0);
        #pragma unroll
        for (int k = 0; k < 8; ++k)
            if (old[k]) scatter_one(pos[k], vals[old[k] - 1] * 0.1f);
    } else {
        for (int k = 0; k < 8; ++k)
            if (base + k < n) {
                int p = flip[base + k];
                int o = atomicExch(&g_aux[p], 0);
                if (o) scatter_one(p, vals[o - 1] * 0.1f);
            }
    }
}

// ============================================================================
// Stage 3: GEMM. CTA 128x32, K-chunk 128, 2-deep TMA pipeline, 2 CTAs/SM.
// ============================================================================
static constexpr int A_SUB = 16384;   // A sub-tile: 128 rows x 128B
static constexpr int B_OFF = 32768;
static constexpr int B_SUB = 4096;    // B sub-tile: 32 rows x 128B
static constexpr int BUF   = 40960;   // A 32KB + B 8KB
static constexpr int SM_TILES = 1024;
static constexpr int GEMM_SMEM = SM_TILES + 2 * BUF;   // 82944 (<113KB for 2/SM)
static constexpr int NC    = I_DIM / 128;   // 32 chunks

__device__ __forceinline__ uint32_t smem_u32(const void* p) {
    uint32_t a;
    asm("{ .reg .u64 t; cvta.to.shared.u64 t, %1; cvt.u32.u64 %0, t; }"
        : "=r"(a) : "l"(p));
    return a;
}
__device__ __forceinline__ void ldsm4(uint32_t* r, uint32_t addr) {
    asm volatile("ldmatrix.sync.aligned.m8n8.x4.shared.b16 {%0,%1,%2,%3}, [%4];"
                 : "=r"(r[0]), "=r"(r[1]), "=r"(r[2]), "=r"(r[3]) : "r"(addr));
}
__device__ __forceinline__ void mma16816(float* c, const uint32_t* a,
                                         uint32_t b0, uint32_t b1) {
    asm volatile(
        "mma.sync.aligned.m16n8k16.row.col.f32.f16.f16.f32 "
        "{%0,%1,%2,%3}, {%4,%5,%6,%7}, {%8,%9}, {%0,%1,%2,%3};"
        : "+f"(c[0]), "+f"(c[1]), "+f"(c[2]), "+f"(c[3])
        : "r"(a[0]), "r"(a[1]), "r"(a[2]), "r"(a[3]), "r"(b0), "r"(b1));
}

#define MBAR_WAIT(mbar_addr, phase) do {                                         \
    uint32_t _mbar = (uint32_t)(mbar_addr);                                      \
    uint32_t _parity = (uint32_t)(phase);                                        \
    uint32_t _done;                                                              \
    asm volatile(                                                                \
        "{\n\t.reg .pred p;\n\t"                                                 \
        "mbarrier.try_wait.parity.acquire.cta.shared::cta.b64 p, [%1], %2;\n\t"  \
        "selp.b32 %0, 1, 0, p;\n\t}"                                             \
        : "=r"(_done) : "r"(_mbar), "r"(_parity) : "memory");                    \
    if (!_done) {                                                                \
        asm volatile(                                                            \
            "{\n\t.reg .pred P1;\n\t"                                            \
            "WL_%=:\n\t"                                                         \
            "mbarrier.try_wait.parity.acquire.cta.shared::cta.b64 P1, [%0], %1, 0x989680;\n\t" \
            "@P1 bra.uni WD_%=;\n\t"                                             \
            "bra.uni WL_%=;\n\t"                                                 \
            "WD_%=:\n\t}"                                                        \
            :: "r"(_mbar), "r"(_parity) : "memory");                             \
    }                                                                            \
} while (0)

// Issue A(32KB) + B(2x4KB halves) bulk copies for chunk c (single thread).
__device__ __forceinline__ void tma_chunk(uint32_t bufb, uint32_t mbar,
                                          int c, int m0, int n0) {
    asm volatile("mbarrier.arrive.expect_tx.shared.b64 _, [%0], %1;"
                 :: "r"(mbar), "r"(40960u) : "memory");
    const char* srcA = reinterpret_cast<const char*>(g_xh)
                     + (size_t)c * 65536 + (m0 >> 7) * 32768;
    // wh group = n0>>6 (64 rows); our 32-row panel = (n0&32)*128B into each sub
    const char* srcB = reinterpret_cast<const char*>(g_wh)
                     + (size_t)c * 1048576 + (n0 >> 6) * 16384
                     + (uint32_t)(n0 & 32) * 128;
    asm volatile(
        "cp.async.bulk.shared::cluster.global.mbarrier::complete_tx::bytes "
        "[%0], [%1], %2, [%3];"
        :: "r"(bufb), "l"(srcA), "r"(32768u), "r"(mbar) : "memory");
    asm volatile(
        "cp.async.bulk.shared::cluster.global.mbarrier::complete_tx::bytes "
        "[%0], [%1], %2, [%3];"
        :: "r"(bufb + B_OFF), "l"(srcB), "r"(4096u), "r"(mbar) : "memory");
    asm volatile(
        "cp.async.bulk.shared::cluster.global.mbarrier::complete_tx::bytes "
        "[%0], [%1], %2, [%3];"
        :: "r"(bufb + B_OFF + B_SUB), "l"(srcB + 8192), "r"(4096u), "r"(mbar)
        : "memory");
}

__global__ void __launch_bounds__(256, 2) gemm_kernel(float* __restrict__ y) {
    extern __shared__ __align__(1024) char smem[];
    const uint32_t sb = smem_u32(smem);
    const int tid = threadIdx.x, lane = tid & 31, wid = tid >> 5;
    const int wm = wid >> 1, wn = wid & 1;          // warp grid 4(M) x 2(N)
    const int n0 = blockIdx.x * 32;
    const int m0 = blockIdx.y * 128;

    if (tid < 2)
        asm volatile("mbarrier.init.shared.b64 [%0], 1;"
                     :: "r"(sb + tid * 8) : "memory");
    __syncthreads();
    if (tid == 0) {
        tma_chunk(sb + SM_TILES + 0 * BUF, sb + 0, 0, m0, n0);
        tma_chunk(sb + SM_TILES + 1 * BUF, sb + 8, 1, m0, n0);
    }

    float acc[2][2][4];
    #pragma unroll
    for (int i = 0; i < 2; ++i)
        #pragma unroll
        for (int j = 0; j < 2; ++j)
            #pragma unroll
            for (int q = 0; q < 4; ++q) acc[i][j][q] = 0.f;

    const int rl = lane & 15;
    const uint32_t kh16 = (uint32_t)(lane >> 4) * 16;
    const uint32_t arow0 = (uint32_t)(wm * 32 + rl) * 128;
    const uint32_t arow1 = arow0 + 16 * 128;
    const uint32_t brow  = (uint32_t)(wn * 16 + rl) * 128;   // 16 B-rows/warp

    for (int c = 0; c < NC; ++c) {
        const int b = c & 1;
        MBAR_WAIT(sb + b * 8, (c >> 1) & 1);
        const uint32_t bb = sb + SM_TILES + b * BUF;

        #pragma unroll
        for (int ks = 0; ks < 8; ++ks) {
            const uint32_t sub_a = bb + (ks >> 2) * A_SUB;
            const uint32_t sub_b = bb + B_OFF + (ks >> 2) * B_SUB;
            const uint32_t kb = (uint32_t)(ks & 3) * 32 + kh16;
            uint32_t ah[2][4], bh[4];
            ldsm4(ah[0], sub_a + SW128(arow0 + kb));
            ldsm4(ah[1], sub_a + SW128(arow1 + kb));
            ldsm4(bh,    sub_b + SW128(brow + kb));
            #pragma unroll
            for (int mi = 0; mi < 2; ++mi) {
                mma16816(acc[mi][0], ah[mi], bh[0], bh[2]);
                mma16816(acc[mi][1], ah[mi], bh[1], bh[3]);
            }
        }
        __syncthreads();   // all warps done with buffer b
        if (tid == 0 && c + 2 < NC)
            tma_chunk(sb + SM_TILES + b * BUF, sb + b * 8, c + 2, m0, n0);
    }

    #pragma unroll
    for (int mi = 0; mi < 2; ++mi) {
        const int row0 = m0 + wm * 32 + mi * 16 + (lane >> 2);
        #pragma unroll
        for (int nb = 0; nb < 2; ++nb) {
            const int col = n0 + wn * 16 + nb * 8 + (lane & 3) * 2;
            *reinterpret_cast<float2*>(y + (size_t)row0 * O_DIM + col) =
                make_float2(acc[mi][nb][0], acc[mi][nb][1]);
            *reinterpret_cast<float2*>(y + (size_t)(row0 + 8) * O_DIM + col) =
                make_float2(acc[mi][nb][2], acc[mi][nb][3]);
        }
    }
}

// ============================================================================
extern "C" void kernel_launch(void* const* d_in, const int* in_sizes, int n_in,
                              void* d_out, int out_size) {
    const float* x    = (const float*)d_in[0];
    const float* w    = (const float*)d_in[1];
    const int*   flip = (const int*)d_in[2];   // JAX x64 disabled -> int32
    const float* vals = (const float*)d_in[3];
    float*       y    = (float*)d_out;
    const int nflip = in_sizes[2];

    stage1_kernel<<<NB_WIN + NB_CX + NB_CW, 256>>>(
        reinterpret_cast<const float4*>(x), reinterpret_cast<const float4*>(w),
        flip, nflip);
    scatter_kernel<<<(nflip + 2047) / 2048, 256>>>(flip, vals, nflip);

    cudaFuncSetAttribute(gemm_kernel, cudaFuncAttributeMaxDynamicSharedMemorySize,
                         GEMM_SMEM);
    gemm_kernel<<<dim3(O_DIM / 32, B_ROWS / 128, 1), 256, GEMM_SMEM>>>(y);
}